// round 4
// baseline (speedup 1.0000x reference)
#include <cuda_runtime.h>
#include <cuda_fp16.h>

#define NN  50000
#define ER  1600000
#define EMB 32
#define HID 128

typedef unsigned long long u64;
struct u64x2 { u64 lo, hi; };

// ---- packed f32x2 helpers (sm_103a FFMA2 path, PTX-only) ----
__device__ __forceinline__ u64 dup2(float a) {
    u64 r; asm("mov.b64 %0, {%1, %1};" : "=l"(r) : "f"(a)); return r;
}
__device__ __forceinline__ u64 packf2(float a, float b) {
    u64 r; asm("mov.b64 %0, {%1, %2};" : "=l"(r) : "f"(a), "f"(b)); return r;
}
__device__ __forceinline__ void ffma2(u64& d, u64 a, u64 b) {
    asm("fma.rn.f32x2 %0, %1, %2, %0;" : "+l"(d) : "l"(a), "l"(b));
}
__device__ __forceinline__ float2 unpackf2(u64 v) {
    float2 r; asm("mov.b64 {%0, %1}, %2;" : "=f"(r.x), "=f"(r.y) : "l"(v)); return r;
}

// ---------------- device scratch (static, no cudaMalloc) ----------------
__device__ int    g_deg[NN];
__device__ float  g_dinv[NN];
__device__ int    g_rowstart[NN];
__device__ int    g_cursor[NN];
__device__ int2   g_edge[ER];            // {src, weight bits} 12.8 MB
__device__ int    g_total;
__device__ float  g_aggemb[NN * EMB];    //  6.4 MB
__device__ __half g_h1h[NN * HID];       // 12.8 MB (fp16 hidden)
__device__ float  g_agg2[NN * HID];      // 25.6 MB

// ---------------- 1) init ----------------
__global__ void k_init() {
    int i = blockIdx.x * 256 + threadIdx.x;
    if (i < NN) g_deg[i] = 1;
    if (i == 0) g_total = 0;
}

// ---------------- 2) degree histogram over dst (2 edges/thread) ----------------
__global__ void k_deg(const int* __restrict__ ei) {
    int t = blockIdx.x * 256 + threadIdx.x;          // t < ER/2
    int2 d2 = reinterpret_cast<const int2*>(ei + ER)[t];
    atomicAdd(&g_deg[d2.x], 1);
    atomicAdd(&g_deg[d2.y], 1);
}

// ---------------- 3) dinv + CSR row allocation (warp-aggregated bump) ----------------
__global__ void k_dinv_alloc() {
    int i    = blockIdx.x * 256 + threadIdx.x;
    int lane = threadIdx.x & 31;
    int cnt  = 0;
    if (i < NN) {
        int d = g_deg[i];
        g_dinv[i] = rsqrtf((float)d);
        cnt = d - 1;
    }
    int incl = cnt;
#pragma unroll
    for (int off = 1; off < 32; off <<= 1) {
        int t = __shfl_up_sync(0xffffffffu, incl, off);
        if (lane >= off) incl += t;
    }
    int total = __shfl_sync(0xffffffffu, incl, 31);
    int base  = 0;
    if (lane == 31) base = atomicAdd(&g_total, total);
    base = __shfl_sync(0xffffffffu, base, 31);
    if (i < NN) {
        int start = base + incl - cnt;
        g_rowstart[i] = start;
        g_cursor[i]   = start;
    }
}

// ---------------- 4) scatter edges + precompute weights (2 edges/thread) ----------------
__global__ void k_scatter(const int* __restrict__ ei) {
    int t = blockIdx.x * 256 + threadIdx.x;          // t < ER/2
    int2 s2 = reinterpret_cast<const int2*>(ei)[t];
    int2 d2 = reinterpret_cast<const int2*>(ei + ER)[t];
    float w0 = g_dinv[s2.x] * g_dinv[d2.x];
    float w1 = g_dinv[s2.y] * g_dinv[d2.y];
    int p0 = atomicAdd(&g_cursor[d2.x], 1);
    int p1 = atomicAdd(&g_cursor[d2.y], 1);
    g_edge[p0] = make_int2(s2.x, __float_as_int(w0));
    g_edge[p1] = make_int2(s2.y, __float_as_int(w1));
}

// ---------------- 5) aggregate embeddings (32-dim, warp per node, MLP=4) ----------------
__global__ void k_agg_emb(const float* __restrict__ emb) {
    int w    = (blockIdx.x * 256 + threadIdx.x) >> 5;
    int lane = threadIdx.x & 31;
    if (w >= NN) return;
    float di  = g_dinv[w];
    float acc = emb[w * EMB + lane] * di * di;       // self loop
    const int2* ep = g_edge + g_rowstart[w];
    int cnt = g_deg[w] - 1;
    int e = 0;
    for (; e + 4 <= cnt; e += 4) {
        int2 q0 = ep[e], q1 = ep[e + 1], q2 = ep[e + 2], q3 = ep[e + 3];
        float r0 = emb[q0.x * EMB + lane];
        float r1 = emb[q1.x * EMB + lane];
        float r2 = emb[q2.x * EMB + lane];
        float r3 = emb[q3.x * EMB + lane];
        acc += r0 * __int_as_float(q0.y);
        acc += r1 * __int_as_float(q1.y);
        acc += r2 * __int_as_float(q2.y);
        acc += r3 * __int_as_float(q3.y);
    }
    for (; e < cnt; e++) {
        int2 q = ep[e];
        acc += emb[q.x * EMB + lane] * __int_as_float(q.y);
    }
    g_aggemb[w * EMB + lane] = acc;
}

// ---------------- 6) GEMM1: h1 = relu(aggemb @ W1 + b1) -> fp16 ----------------
__global__ void k_gemm1(const float* __restrict__ W1, const float* __restrict__ b1) {
    __shared__ float Ws[EMB * HID];   // 16 KB
    __shared__ float As[16 * EMB];    //  2 KB
    for (int idx = threadIdx.x; idx < EMB * HID; idx += 256) Ws[idx] = W1[idx];

    int tcol = (threadIdx.x & 31) * 4;        // 0..124
    int trow = (threadIdx.x >> 5) * 2;        // 0..14
    u64 bias01 = packf2(__ldg(&b1[tcol]),     __ldg(&b1[tcol + 1]));
    u64 bias23 = packf2(__ldg(&b1[tcol + 2]), __ldg(&b1[tcol + 3]));

    const int NT = NN / 16;                   // 3125 exact
    for (int t = blockIdx.x; t < NT; t += gridDim.x) {
        int row0 = t * 16;
        __syncthreads();
        for (int idx = threadIdx.x; idx < 16 * EMB / 4; idx += 256)
            ((float4*)As)[idx] = ((const float4*)g_aggemb)[row0 * (EMB / 4) + idx];
        __syncthreads();

        u64 acc[2][2] = {{bias01, bias23}, {bias01, bias23}};
#pragma unroll
        for (int k = 0; k < EMB; k++) {
            u64x2 w = *reinterpret_cast<const u64x2*>(&Ws[k * HID + tcol]);
            u64 a0 = dup2(As[trow * EMB + k]);
            u64 a1 = dup2(As[(trow + 1) * EMB + k]);
            ffma2(acc[0][0], a0, w.lo); ffma2(acc[0][1], a0, w.hi);
            ffma2(acc[1][0], a1, w.lo); ffma2(acc[1][1], a1, w.hi);
        }
#pragma unroll
        for (int r = 0; r < 2; r++) {
            float2 p01 = unpackf2(acc[r][0]);
            float2 p23 = unpackf2(acc[r][1]);
            __half2 h01 = __floats2half2_rn(fmaxf(p01.x, 0.f), fmaxf(p01.y, 0.f));
            __half2 h23 = __floats2half2_rn(fmaxf(p23.x, 0.f), fmaxf(p23.y, 0.f));
            uint2 st;
            st.x = *reinterpret_cast<unsigned*>(&h01);
            st.y = *reinterpret_cast<unsigned*>(&h23);
            *reinterpret_cast<uint2*>(&g_h1h[(row0 + trow + r) * HID + tcol]) = st;
        }
    }
}

// ---------------- 7) aggregate h1 (fp16 gather, fp32 accumulate, MLP=4) ----------------
__global__ void k_agg_h1() {
    int w    = (blockIdx.x * 256 + threadIdx.x) >> 5;
    int lane = threadIdx.x & 31;
    if (w >= NN) return;
    float di = g_dinv[w];
    const uint2* hv = reinterpret_cast<const uint2*>(g_h1h);  // 4 halves / uint2
    uint2 v = hv[w * 32 + lane];
    float2 vl = __half22float2(*reinterpret_cast<__half2*>(&v.x));
    float2 vh = __half22float2(*reinterpret_cast<__half2*>(&v.y));
    float  sw = di * di;
    float4 acc = make_float4(vl.x * sw, vl.y * sw, vh.x * sw, vh.y * sw);
    const int2* ep = g_edge + g_rowstart[w];
    int cnt = g_deg[w] - 1;
    int e = 0;
    for (; e + 4 <= cnt; e += 4) {
        int2 q0 = ep[e], q1 = ep[e + 1], q2 = ep[e + 2], q3 = ep[e + 3];
        uint2 u0 = hv[q0.x * 32 + lane];
        uint2 u1 = hv[q1.x * 32 + lane];
        uint2 u2 = hv[q2.x * 32 + lane];
        uint2 u3 = hv[q3.x * 32 + lane];
#define ACCUM(u, qy)  do {                                              \
        float ns = __int_as_float(qy);                                   \
        float2 ul = __half22float2(*reinterpret_cast<__half2*>(&(u).x)); \
        float2 uh = __half22float2(*reinterpret_cast<__half2*>(&(u).y)); \
        acc.x += ul.x * ns; acc.y += ul.y * ns;                          \
        acc.z += uh.x * ns; acc.w += uh.y * ns; } while (0)
        ACCUM(u0, q0.y); ACCUM(u1, q1.y); ACCUM(u2, q2.y); ACCUM(u3, q3.y);
    }
    for (; e < cnt; e++) {
        int2 q = ep[e];
        uint2 u = hv[q.x * 32 + lane];
        ACCUM(u, q.y);
    }
#undef ACCUM
    reinterpret_cast<float4*>(g_agg2)[w * 32 + lane] = acc;
}

// ---------------- 8) GEMM2: out = agg2 @ W2 + b2, col-halved, FFMA2 ----------------
__global__ void k_gemm2(const float* __restrict__ W2, const float* __restrict__ b2,
                        float* __restrict__ out) {
    __shared__ float Ws[HID * 64];    // 32 KB
    __shared__ float As[32 * HID];    // 16 KB (48 KB total)
    int half = blockIdx.x & 1;
    for (int idx = threadIdx.x; idx < HID * 64; idx += 256) {
        int k = idx >> 6, c = idx & 63;
        Ws[idx] = W2[k * HID + half * 64 + c];
    }
    int tcol = (threadIdx.x & 15) * 4;   // 0..60 within the half
    int trow = (threadIdx.x >> 4) * 2;   // 0..30
    u64 bias01 = packf2(__ldg(&b2[half * 64 + tcol]),     __ldg(&b2[half * 64 + tcol + 1]));
    u64 bias23 = packf2(__ldg(&b2[half * 64 + tcol + 2]), __ldg(&b2[half * 64 + tcol + 3]));

    const int NT = (NN + 31) / 32;       // 1563
    for (int t = blockIdx.x >> 1; t < NT; t += (gridDim.x >> 1)) {
        int row0 = t * 32;
        __syncthreads();
        for (int idx = threadIdx.x; idx < 32 * HID / 4; idx += 256) {
            int gr = row0 + (idx >> 5);
            ((float4*)As)[idx] = (gr < NN)
                ? ((const float4*)g_agg2)[gr * 32 + (idx & 31)]
                : make_float4(0.f, 0.f, 0.f, 0.f);
        }
        __syncthreads();

        u64 acc[2][2] = {{bias01, bias23}, {bias01, bias23}};
#pragma unroll 8
        for (int k = 0; k < HID; k++) {
            u64x2 w = *reinterpret_cast<const u64x2*>(&Ws[k * 64 + tcol]);
            u64 a0 = dup2(As[trow * HID + k]);
            u64 a1 = dup2(As[(trow + 1) * HID + k]);
            ffma2(acc[0][0], a0, w.lo); ffma2(acc[0][1], a0, w.hi);
            ffma2(acc[1][0], a1, w.lo); ffma2(acc[1][1], a1, w.hi);
        }
#pragma unroll
        for (int r = 0; r < 2; r++) {
            int gr = row0 + trow + r;
            if (gr < NN) {
                float2 p01 = unpackf2(acc[r][0]);
                float2 p23 = unpackf2(acc[r][1]);
                float4 o = make_float4(p01.x, p01.y, p23.x, p23.y);
                *reinterpret_cast<float4*>(&out[gr * HID + half * 64 + tcol]) = o;
            }
        }
    }
}

// ---------------- host launcher ----------------
extern "C" void kernel_launch(void* const* d_in, const int* in_sizes, int n_in,
                              void* d_out, int out_size) {
    const int*   ei  = (const int*)d_in[1];
    const float* emb = (const float*)d_in[2];
    const float* W1  = (const float*)d_in[3];
    const float* b1  = (const float*)d_in[4];
    const float* W2  = (const float*)d_in[5];
    const float* b2  = (const float*)d_in[6];
    float* out = (float*)d_out;

    k_init      <<<(NN + 255) / 256, 256>>>();
    k_deg       <<<ER / 2 / 256, 256>>>(ei);       // 3125 blocks
    k_dinv_alloc<<<(NN + 255) / 256, 256>>>();
    k_scatter   <<<ER / 2 / 256, 256>>>(ei);       // 3125 blocks
    k_agg_emb   <<<(NN * 32) / 256, 256>>>(emb);
    k_gemm1     <<<592, 256>>>(W1, b1);
    k_agg_h1    <<<(NN * 32) / 256, 256>>>();
    k_gemm2     <<<592, 256>>>(W2, b2, out);
}